// round 15
// baseline (speedup 1.0000x reference)
#include <cuda_runtime.h>
#include <cuda_bf16.h>
#include <cstdint>

#define BB 8
#define CC 64
#define HH 128
#define WW 128
#define HWSZ (HH*WW)
#define KOFF 18

// ---- scratch (no allocations allowed) ----
__device__ float g_offset[BB*KOFF*HWSZ];   // post-PReLU offsets [B,18,H,W]
__device__ float g_atten [BB*CC*HWSZ];     // softmax(conv) [B,64,H,W]
__device__ __align__(16) __nv_bfloat16 g_xtb[BB*HWSZ*CC];  // x NHWC bf16
__device__ __align__(16) __nv_bfloat16 g_Bimg[576*88];     // B weights [k=576][n=88] bf16
__device__ float g_dummy[1];

typedef unsigned long long u64;

__device__ __forceinline__ uint32_t smem_to_u32(const void* p){
    uint32_t a;
    asm("{ .reg .u64 t; cvta.to.shared.u64 t, %1; cvt.u32.u64 %0, t; }" : "=r"(a) : "l"(p));
    return a;
}
__device__ __forceinline__ float bfLO(uint32_t u){ return __uint_as_float(u << 16); }
__device__ __forceinline__ float bfHI(uint32_t u){ return __uint_as_float(u & 0xffff0000u); }
__device__ __forceinline__ u64 pk2(float lo, float hi){
    u64 r; asm("mov.b64 %0, {%1,%2};" : "=l"(r) : "f"(lo), "f"(hi)); return r;
}
__device__ __forceinline__ float2 uf2(u64 v){
    float2 f; asm("mov.b64 {%0,%1}, %2;" : "=f"(f.x), "=f"(f.y) : "l"(v)); return f;
}
__device__ __forceinline__ u64 fma2(u64 a, u64 b, u64 c){
    u64 d; asm("fma.rn.f32x2 %0, %1, %2, %3;" : "=l"(d) : "l"(a), "l"(b), "l"(c)); return d;
}

#define LDSM_X4(r, addr) \
    asm volatile("ldmatrix.sync.aligned.m8n8.x4.shared.b16 {%0,%1,%2,%3}, [%4];" \
        : "=r"((r)[0]),"=r"((r)[1]),"=r"((r)[2]),"=r"((r)[3]) : "r"(addr))
#define LDSM_X2T(r, addr) \
    asm volatile("ldmatrix.sync.aligned.m8n8.x2.trans.shared.b16 {%0,%1}, [%2];" \
        : "=r"((r)[0]),"=r"((r)[1]) : "r"(addr))

__device__ __forceinline__ void mma16816(float* d, const uint32_t* a, const uint32_t* b){
    asm volatile("mma.sync.aligned.m16n8k16.row.col.f32.bf16.bf16.f32 "
        "{%0,%1,%2,%3}, {%4,%5,%6,%7}, {%8,%9}, {%0,%1,%2,%3};"
        : "+f"(d[0]), "+f"(d[1]), "+f"(d[2]), "+f"(d[3])
        : "r"(a[0]), "r"(a[1]), "r"(a[2]), "r"(a[3]), "r"(b[0]), "r"(b[1]));
}

// convMMA6 smem (bytes): sx 3 rows x 130 px x 144B = 56160; B single buf 11264.
// sD (88 x 132 f32 = 46464B) aliases [0,...) after mainloop. Total 67424 -> 3 blk/SM.
#define SB6   56160
#define SMEM6 (56160 + 11264)

// ---------------------------------------------------------------------------
__global__ void k_prepB(const float* __restrict__ cw, const float* __restrict__ offw)
{
    int i = blockIdx.x*256 + threadIdx.x;
    if (i >= 576*88) return;
    int k = i / 88, n = i - k*88;
    int tap = k >> 6, cin = k & 63;
    float v = 0.f;
    if (n < 64)      v = cw [(n*CC + cin)*9 + tap];
    else if (n < 82) v = offw[((n - 64)*CC + cin)*9 + tap];
    g_Bimg[i] = __float2bfloat16(v);
}

__global__ void k_dummy() { if (threadIdx.x == 0) g_dummy[0] = 0.f; }

// ---------------------------------------------------------------------------
// T: transpose x NCHW f32 -> NHWC bf16. grid 2048 = (b,h,chalf).
// ---------------------------------------------------------------------------
__global__ __launch_bounds__(256) void k_transpose(const float* __restrict__ x)
{
    __shared__ float s[32][129];
    int t = threadIdx.x;
    int b = blockIdx.x >> 8, h = (blockIdx.x >> 1) & 127, ch = blockIdx.x & 1;
    const float* xb = x + (b*CC + ch*32)*HWSZ + h*WW;
    for (int i = t; i < 32*32; i += 256) {
        int c = i >> 5, wq = i & 31;
        float4 v = *(const float4*)(xb + c*HWSZ + wq*4);
        s[c][wq*4 + 0] = v.x; s[c][wq*4 + 1] = v.y;
        s[c][wq*4 + 2] = v.z; s[c][wq*4 + 3] = v.w;
    }
    __syncthreads();
    __nv_bfloat16* ob = g_xtb + (size_t)(b*HH + h)*WW*CC + ch*32;
    for (int i = t; i < 128*16; i += 256) {
        int w = i >> 4, cp = i & 15;
        uint32_t p;
        asm("cvt.rn.satfinite.bf16x2.f32 %0, %1, %2;"
            : "=r"(p) : "f"(s[cp*2 + 1][w]), "f"(s[cp*2][w]));
        *(uint32_t*)(ob + w*CC + cp*2) = p;
    }
}

// ---------------------------------------------------------------------------
// convMMA6: per (b,h) row, M=128, N=88, K=576 bf16 HMMA; warp = 16 px;
// single-buffered B tap chunk -> smem 67.4KB -> 3 blocks/SM (24 warps).
// ---------------------------------------------------------------------------
__global__ __launch_bounds__(256, 3) void k_convMMA6(
    const float* __restrict__ offb, const float* __restrict__ pa_)
{
    extern __shared__ char smem[];
    uint32_t sb = smem_to_u32(smem);
    int t = threadIdx.x, wid = t >> 5, lane = t & 31;
    int b = blockIdx.x >> 7, h = blockIdx.x & 127;

    // stage sx: rows h-1..h+1, 130 px, 64ch bf16, stride 144B — pure copy
    for (int i = t; i < 3*130*8; i += 256) {
        int rp = i >> 3, q = i & 7;
        int r = rp / 130, pxp = rp - r*130;
        int y = h + r - 1, xc = pxp - 1;
        uint4 v = make_uint4(0u, 0u, 0u, 0u);
        if (y >= 0 && y < HH && xc >= 0 && xc < WW)
            v = *(const uint4*)(g_xtb + ((size_t)(b*HH + y)*WW + xc)*CC + q*8);
        *(uint4*)(smem + rp*144 + q*16) = v;
    }

    float acc[11][4];
    #pragma unroll
    for (int nt = 0; nt < 11; nt++)
        #pragma unroll
        for (int j = 0; j < 4; j++) acc[nt][j] = 0.f;

    uint32_t l15  = lane & 15;
    uint32_t hi16 = (uint32_t)(lane >> 4) * 16;

    #pragma unroll 1
    for (int tap = 0; tap < 9; tap++) {
        int ky = tap / 3, kx = tap - ky*3;
        __syncthreads();            // protect B buffer from previous tap's readers
        {
            const uint4* srcB = (const uint4*)g_Bimg + tap*704;
            uint4* dstB = (uint4*)(smem + SB6);
            for (int i = t; i < 704; i += 256) dstB[i] = srcB[i];
        }
        __syncthreads();
        uint32_t rowA = sb + (uint32_t)(ky*130 + kx + wid*16 + (int)l15)*144 + hi16;
        uint32_t rowB = sb + SB6 + l15*176;
        #pragma unroll
        for (int s = 0; s < 4; s++) {
            uint32_t a[4];
            LDSM_X4(a, rowA + s*32);
            uint32_t bA = rowB + (uint32_t)s*16*176;
            #pragma unroll
            for (int nt = 0; nt < 11; nt++) {
                uint32_t bf[2];
                LDSM_X2T(bf, bA + nt*16);
                mma16816(acc[nt], a, bf);
            }
        }
    }

    // fragments -> sD[oc][px] (aliases sx; dead now)
    __syncthreads();
    float* sD = (float*)(smem);
    {
        int n0 = (lane & 3)*2;
        int px = wid*16 + (lane >> 2);
        #pragma unroll
        for (int nt = 0; nt < 11; nt++) {
            int n = nt*8 + n0;
            sD[n*132 + px]           = acc[nt][0];
            sD[(n + 1)*132 + px]     = acc[nt][1];
            sD[n*132 + px + 8]       = acc[nt][2];
            sD[(n + 1)*132 + px + 8] = acc[nt][3];
        }
    }
    __syncthreads();

    float pa = pa_[0];
    for (int oc = wid; oc < 82; oc += 8) {
        float v[4];
        #pragma unroll
        for (int j = 0; j < 4; j++) v[j] = sD[oc*132 + lane + 32*j];
        if (oc < 64) {
            float m = fmaxf(fmaxf(v[0], v[1]), fmaxf(v[2], v[3]));
            #pragma unroll
            for (int s = 16; s > 0; s >>= 1)
                m = fmaxf(m, __shfl_xor_sync(0xffffffffu, m, s));
            float e[4]; float sum = 0.f;
            #pragma unroll
            for (int j = 0; j < 4; j++) { e[j] = __expf(v[j] - m); sum += e[j]; }
            #pragma unroll
            for (int s = 16; s > 0; s >>= 1)
                sum += __shfl_xor_sync(0xffffffffu, sum, s);
            float inv = 1.0f / sum;
            int base = ((b*CC + oc)*HH + h)*WW + lane;
            #pragma unroll
            for (int j = 0; j < 4; j++) g_atten[base + 32*j] = e[j]*inv;
        } else {
            int o2 = oc - 64;
            float bo = offb[o2];
            int base = ((b*KOFF + o2)*HH + h)*WW + lane;
            #pragma unroll
            for (int j = 0; j < 4; j++) {
                float u = v[j] + bo;
                g_offset[base + 32*j] = u >= 0.f ? u : pa*u;
            }
        }
    }
}

// ---------------------------------------------------------------------------
// H2: deformable grouped conv (unchanged from R14).
// ---------------------------------------------------------------------------
#define SFS 36
#define SWR 147
__global__ __launch_bounds__(256, 3) void k_deformH2(
    const float* __restrict__ x, const float* __restrict__ dw,
    const float* __restrict__ db, float* __restrict__ out)
{
    extern __shared__ char smH[];
    uint32_t* sco = (uint32_t*)smH;
    u64* sw2      = (u64*)(smH + 9216);
    float* sfeat  = (float*)(smH + 9216 + 16*SWR*8);

    int t = threadIdx.x;
    int b  = blockIdx.x >> 9;
    int h  = (blockIdx.x >> 2) & 127;
    int q  = blockIdx.x & 3;
    int px0 = q*32;

    for (int i = t; i < 288; i += 256) {
        int tap = i >> 5, pl = i & 31;
        int ky = tap / 3, kx = tap - ky*3;
        int w = px0 + pl;
        float dy = g_offset[(b*KOFF + 2*tap)*HWSZ + h*WW + w];
        float dx = g_offset[(b*KOFF + 2*tap + 1)*HWSZ + h*WW + w];
        float ys = (float)(h - 1 + ky) + dy;
        float xs = (float)(w - 1 + kx) + dx;
        float yf = floorf(ys), xf = floorf(xs);
        float ay = ys - yf, ax = xs - xf;
        int iy0 = (int)yf, ix0 = (int)xf;
        float my0 = (iy0 >= 0  && iy0 < HH)     ? 1.f : 0.f;
        float my1 = (iy0 >= -1 && iy0 + 1 < HH) ? 1.f : 0.f;
        float mx0 = (ix0 >= 0  && ix0 < WW)     ? 1.f : 0.f;
        float mx1 = (ix0 >= -1 && ix0 + 1 < WW) ? 1.f : 0.f;
        int cy0 = min(max(iy0, 0), HH - 1), cy1 = min(max(iy0 + 1, 0), HH - 1);
        int cx0 = min(max(ix0, 0), WW - 1), cx1 = min(max(ix0 + 1, 0), WW - 1);
        uint4 I = make_uint4((uint32_t)((cy0*WW + cx0)*CC),
                             (uint32_t)((cy0*WW + cx1)*CC),
                             (uint32_t)((cy1*WW + cx0)*CC),
                             (uint32_t)((cy1*WW + cx1)*CC));
        uint4 Cq = make_uint4(__float_as_uint((1.f - ay)*(1.f - ax)*my0*mx0),
                              __float_as_uint((1.f - ay)*ax*my0*mx1),
                              __float_as_uint(ay*(1.f - ax)*my1*mx0),
                              __float_as_uint(ay*ax*my1*mx1));
        *(uint4*)(sco + i*8)     = I;
        *(uint4*)(sco + i*8 + 4) = Cq;
    }
    for (int i = t; i < 16*9*16; i += 256) {
        int gh = i / 144; int rem = i - gh*144;
        int tap = rem >> 4; int j = rem & 15;
        int ci = j >> 2, p = j & 3;
        int g = gh >> 1, half = gh & 1;
        int base = ((g*8 + 2*p)*8 + half*4 + ci)*9 + tap;
        sw2[gh*SWR + tap*16 + ci*4 + p] = pk2(dw[base], dw[base + 72]);
    }
    __syncthreads();

    int pl = t >> 4, gh = t & 15;
    int g = gh >> 1, half = gh & 1;

    u64 acc0[4], acc1[4];
    #pragma unroll
    for (int p = 0; p < 4; p++) {
        u64 bo = half ? 0ULL : pk2(db[g*8 + 2*p], db[g*8 + 2*p + 1]);
        acc0[p] = bo; acc1[p] = bo;
    }

    const __nv_bfloat16* xgb = g_xtb + (size_t)b*HWSZ*CC + g*8 + half*4;
    const u64* sw2g = sw2 + gh*SWR;

    #pragma unroll 1
    for (int k = 0; k < 9; k++) {
        u64 W2[16];
        {
            const u64* wt = sw2g + k*16;
            #pragma unroll
            for (int j = 0; j < 16; j++) W2[j] = wt[j];
        }
        #pragma unroll
        for (int p2 = 0; p2 < 2; p2++) {
            int plo = pl + p2*16;
            u64* ac = p2 ? acc1 : acc0;
            uint4 I  = *(const uint4*)(sco + (k*32 + plo)*8);
            uint4 Cq = *(const uint4*)(sco + (k*32 + plo)*8 + 4);
            float c00 = __uint_as_float(Cq.x), c01 = __uint_as_float(Cq.y);
            float c10 = __uint_as_float(Cq.z), c11 = __uint_as_float(Cq.w);
            uint2 A  = *(const uint2*)(xgb + I.x);
            uint2 Bv = *(const uint2*)(xgb + I.y);
            uint2 Cv = *(const uint2*)(xgb + I.z);
            uint2 D  = *(const uint2*)(xgb + I.w);
            float s0 = c00*bfLO(A.x) + c01*bfLO(Bv.x) + c10*bfLO(Cv.x) + c11*bfLO(D.x);
            float s1 = c00*bfHI(A.x) + c01*bfHI(Bv.x) + c10*bfHI(Cv.x) + c11*bfHI(D.x);
            float s2 = c00*bfLO(A.y) + c01*bfLO(Bv.y) + c10*bfLO(Cv.y) + c11*bfLO(D.y);
            float s3 = c00*bfHI(A.y) + c01*bfHI(Bv.y) + c10*bfHI(Cv.y) + c11*bfHI(D.y);
            u64 sp;
            sp = pk2(s0, s0);
            ac[0] = fma2(W2[0],  sp, ac[0]); ac[1] = fma2(W2[1],  sp, ac[1]);
            ac[2] = fma2(W2[2],  sp, ac[2]); ac[3] = fma2(W2[3],  sp, ac[3]);
            sp = pk2(s1, s1);
            ac[0] = fma2(W2[4],  sp, ac[0]); ac[1] = fma2(W2[5],  sp, ac[1]);
            ac[2] = fma2(W2[6],  sp, ac[2]); ac[3] = fma2(W2[7],  sp, ac[7 - 4]);
            sp = pk2(s2, s2);
            ac[0] = fma2(W2[8],  sp, ac[0]); ac[1] = fma2(W2[9],  sp, ac[1]);
            ac[2] = fma2(W2[10], sp, ac[2]); ac[3] = fma2(W2[11], sp, ac[3]);
            sp = pk2(s3, s3);
            ac[0] = fma2(W2[12], sp, ac[0]); ac[1] = fma2(W2[13], sp, ac[1]);
            ac[2] = fma2(W2[14], sp, ac[2]); ac[3] = fma2(W2[15], sp, ac[3]);
        }
    }

    #pragma unroll
    for (int p = 0; p < 4; p++) {
        float2 a0 = uf2(acc0[p]), a1 = uf2(acc1[p]);
        a0.x += __shfl_xor_sync(0xffffffffu, a0.x, 1);
        a0.y += __shfl_xor_sync(0xffffffffu, a0.y, 1);
        a1.x += __shfl_xor_sync(0xffffffffu, a1.x, 1);
        a1.y += __shfl_xor_sync(0xffffffffu, a1.y, 1);
        if (half == 0) {
            sfeat[(g*8 + 2*p)*SFS + pl]          = a0.x;
            sfeat[(g*8 + 2*p + 1)*SFS + pl]      = a0.y;
            sfeat[(g*8 + 2*p)*SFS + pl + 16]     = a1.x;
            sfeat[(g*8 + 2*p + 1)*SFS + pl + 16] = a1.y;
        }
    }
    __syncthreads();

    #pragma unroll
    for (int it = 0; it < 2; it++) {
        int idx = t + it*256;
        int oc = idx >> 3, p4 = idx & 7;
        float4 f = *(const float4*)(sfeat + oc*SFS + p4*4);
        int base = ((b*CC + oc)*HH + h)*WW + px0 + p4*4;
        float4 at = *(const float4*)(g_atten + base);
        float4 xv = *(const float4*)(x + base);
        float4 ov = make_float4(fmaf(at.x, f.x, xv.x), fmaf(at.y, f.y, xv.y),
                                fmaf(at.z, f.z, xv.z), fmaf(at.w, f.w, xv.w));
        *(float4*)(out + base) = ov;
    }
}

extern "C" void kernel_launch(void* const* d_in, const int* in_sizes, int n_in,
                              void* d_out, int out_size)
{
    const float* x    = (const float*)d_in[0];
    const float* offw = (const float*)d_in[1];
    const float* offb = (const float*)d_in[2];
    const float* pa   = (const float*)d_in[3];
    const float* dw   = (const float*)d_in[4];
    const float* db   = (const float*)d_in[5];
    const float* cw   = (const float*)d_in[6];
    float* out = (float*)d_out;

    const int smemH = 9216 + 16*SWR*8 + 64*SFS*4;   // 37248

    cudaFuncSetAttribute(k_convMMA6, cudaFuncAttributeMaxDynamicSharedMemorySize, SMEM6);
    cudaFuncSetAttribute(k_deformH2, cudaFuncAttributeMaxDynamicSharedMemorySize, smemH);

    k_prepB<<<198, 256>>>(cw, offw);
    k_transpose<<<2048, 256>>>(x);
    k_dummy<<<1, 32>>>();
    k_convMMA6<<<1024, 256, SMEM6>>>(offb, pa);        // 4th launch -> ncu capture
    k_deformH2<<<4096, 256, smemH>>>(x, dw, db, out);
}

// round 16
// speedup vs baseline: 1.0688x; 1.0688x over previous
#include <cuda_runtime.h>
#include <cuda_bf16.h>
#include <cstdint>

#define BB 8
#define CC 64
#define HH 128
#define WW 128
#define HWSZ (HH*WW)
#define KOFF 18

// ---- scratch (no allocations allowed) ----
__device__ float g_offset[BB*KOFF*HWSZ];   // post-PReLU offsets [B,18,H,W]
__device__ float g_atten [BB*CC*HWSZ];     // softmax(conv) [B,64,H,W]
__device__ __align__(16) __nv_bfloat16 g_xtb[BB*HWSZ*CC];  // x NHWC bf16
__device__ __align__(16) __nv_bfloat16 g_Bimg[576*88];     // B weights [k=576][n=88] bf16
__device__ float g_dummy[1];

typedef unsigned long long u64;

__device__ __forceinline__ uint32_t smem_to_u32(const void* p){
    uint32_t a;
    asm("{ .reg .u64 t; cvta.to.shared.u64 t, %1; cvt.u32.u64 %0, t; }" : "=r"(a) : "l"(p));
    return a;
}
__device__ __forceinline__ float bfLO(uint32_t u){ return __uint_as_float(u << 16); }
__device__ __forceinline__ float bfHI(uint32_t u){ return __uint_as_float(u & 0xffff0000u); }
__device__ __forceinline__ u64 pk2(float lo, float hi){
    u64 r; asm("mov.b64 %0, {%1,%2};" : "=l"(r) : "f"(lo), "f"(hi)); return r;
}
__device__ __forceinline__ float2 uf2(u64 v){
    float2 f; asm("mov.b64 {%0,%1}, %2;" : "=f"(f.x), "=f"(f.y) : "l"(v)); return f;
}
__device__ __forceinline__ u64 fma2(u64 a, u64 b, u64 c){
    u64 d; asm("fma.rn.f32x2 %0, %1, %2, %3;" : "=l"(d) : "l"(a), "l"(b), "l"(c)); return d;
}

#define LDSM_X4(r, addr) \
    asm volatile("ldmatrix.sync.aligned.m8n8.x4.shared.b16 {%0,%1,%2,%3}, [%4];" \
        : "=r"((r)[0]),"=r"((r)[1]),"=r"((r)[2]),"=r"((r)[3]) : "r"(addr))
#define LDSM_X2T(r, addr) \
    asm volatile("ldmatrix.sync.aligned.m8n8.x2.trans.shared.b16 {%0,%1}, [%2];" \
        : "=r"((r)[0]),"=r"((r)[1]) : "r"(addr))
#define LDSM_X4T(r, addr) \
    asm volatile("ldmatrix.sync.aligned.m8n8.x4.trans.shared.b16 {%0,%1,%2,%3}, [%4];" \
        : "=r"((r)[0]),"=r"((r)[1]),"=r"((r)[2]),"=r"((r)[3]) : "r"(addr))

#define CP_ASYNC16(daddr, src) \
    asm volatile("cp.async.cg.shared.global [%0], [%1], 16;" \
        :: "r"(daddr), "l"(src) : "memory")
#define CP_COMMIT() asm volatile("cp.async.commit_group;" ::: "memory")
#define CP_WAIT0()  asm volatile("cp.async.wait_group 0;" ::: "memory")

__device__ __forceinline__ void mma16816(float* d, const uint32_t* a, const uint32_t* b){
    asm volatile("mma.sync.aligned.m16n8k16.row.col.f32.bf16.bf16.f32 "
        "{%0,%1,%2,%3}, {%4,%5,%6,%7}, {%8,%9}, {%0,%1,%2,%3};"
        : "+f"(d[0]), "+f"(d[1]), "+f"(d[2]), "+f"(d[3])
        : "r"(a[0]), "r"(a[1]), "r"(a[2]), "r"(a[3]), "r"(b[0]), "r"(b[1]));
}

// convMMA7 smem (bytes): sx 4 rows x 130 px x 144B = 74880; B dbuf 2x11264.
// sD (88 x 264 f32 = 92928B) aliases [0,...) after mainloop.
#define SB7   74880
#define SMEM7 (74880 + 22528)

// ---------------------------------------------------------------------------
__global__ void k_prepB(const float* __restrict__ cw, const float* __restrict__ offw)
{
    int i = blockIdx.x*256 + threadIdx.x;
    if (i >= 576*88) return;
    int k = i / 88, n = i - k*88;
    int tap = k >> 6, cin = k & 63;
    float v = 0.f;
    if (n < 64)      v = cw [(n*CC + cin)*9 + tap];
    else if (n < 82) v = offw[((n - 64)*CC + cin)*9 + tap];
    g_Bimg[i] = __float2bfloat16(v);
}

__global__ void k_dummy() { if (threadIdx.x == 0) g_dummy[0] = 0.f; }

// ---------------------------------------------------------------------------
// T: transpose x NCHW f32 -> NHWC bf16. grid 2048 = (b,h,chalf).
// ---------------------------------------------------------------------------
__global__ __launch_bounds__(256) void k_transpose(const float* __restrict__ x)
{
    __shared__ float s[32][129];
    int t = threadIdx.x;
    int b = blockIdx.x >> 8, h = (blockIdx.x >> 1) & 127, ch = blockIdx.x & 1;
    const float* xb = x + (b*CC + ch*32)*HWSZ + h*WW;
    for (int i = t; i < 32*32; i += 256) {
        int c = i >> 5, wq = i & 31;
        float4 v = *(const float4*)(xb + c*HWSZ + wq*4);
        s[c][wq*4 + 0] = v.x; s[c][wq*4 + 1] = v.y;
        s[c][wq*4 + 2] = v.z; s[c][wq*4 + 3] = v.w;
    }
    __syncthreads();
    __nv_bfloat16* ob = g_xtb + (size_t)(b*HH + h)*WW*CC + ch*32;
    for (int i = t; i < 128*16; i += 256) {
        int w = i >> 4, cp = i & 15;
        uint32_t p;
        asm("cvt.rn.satfinite.bf16x2.f32 %0, %1, %2;"
            : "=r"(p) : "f"(s[cp*2 + 1][w]), "f"(s[cp*2][w]));
        *(uint32_t*)(ob + w*CC + cp*2) = p;
    }
}

// ---------------------------------------------------------------------------
// convMMA7: M=256 (2 rows), N=88, K=576 bf16 HMMA. Warp = 32 px = 2 A-tiles
// sharing each B fragment. cp.async double-buffered B (overlapped), x4.trans
// B fragment loads (2 n-tiles per LDSM). grid 512 = (b, h-pair).
// ---------------------------------------------------------------------------
__global__ __launch_bounds__(256, 2) void k_convMMA7(
    const float* __restrict__ offb, const float* __restrict__ pa_)
{
    extern __shared__ char smem[];
    uint32_t sb = smem_to_u32(smem);
    int t = threadIdx.x, wid = t >> 5, lane = t & 31;
    int b = blockIdx.x >> 6, hp = blockIdx.x & 63;
    int h0 = hp*2;

    // preload B tap 0 (async) while staging sx
    {
        uint32_t d0 = sb + SB7;
        const uint4* s0 = (const uint4*)g_Bimg;
        for (int i = t; i < 704; i += 256) CP_ASYNC16(d0 + i*16, s0 + i);
        CP_COMMIT();
    }
    // stage sx: rows h0-1..h0+2 (4 rows), 130 px, 64ch bf16, stride 144B
    for (int i = t; i < 4*130*8; i += 256) {
        int rp = i >> 3, q = i & 7;
        int r = rp / 130, pxp = rp - r*130;
        int y = h0 + r - 1, xc = pxp - 1;
        uint4 v = make_uint4(0u, 0u, 0u, 0u);
        if (y >= 0 && y < HH && xc >= 0 && xc < WW)
            v = *(const uint4*)(g_xtb + ((size_t)(b*HH + y)*WW + xc)*CC + q*8);
        *(uint4*)(smem + rp*144 + q*16) = v;
    }
    CP_WAIT0();
    __syncthreads();

    float acc[2][11][4];
    #pragma unroll
    for (int a = 0; a < 2; a++)
        #pragma unroll
        for (int nt = 0; nt < 11; nt++)
            #pragma unroll
            for (int j = 0; j < 4; j++) acc[a][nt][j] = 0.f;

    uint32_t l15  = lane & 15;
    uint32_t hi16 = (uint32_t)(lane >> 4) * 16;
    int orow = wid >> 2, pxq = (wid & 3)*32;

    #pragma unroll 1
    for (int tap = 0; tap < 9; tap++) {
        int ky = tap / 3, kx = tap - ky*3;
        uint32_t bbase = sb + SB7 + (uint32_t)(tap & 1)*11264;
        // async prefetch next tap's B into the other buffer (overlaps MMAs)
        if (tap < 8) {
            const uint4* srcB = (const uint4*)g_Bimg + (tap + 1)*704;
            uint32_t dstB = sb + SB7 + ((tap + 1) & 1)*11264u;
            for (int i = t; i < 704; i += 256) CP_ASYNC16(dstB + i*16, srcB + i);
            CP_COMMIT();
        }
        uint32_t rowA0 = sb + (uint32_t)((orow + ky)*130 + kx + pxq + (int)l15)*144 + hi16;
        uint32_t rowB4 = bbase + l15*176 + hi16;   // x4T: lanes 16-31 -> +16B col
        uint32_t rowB2 = bbase + l15*176;          // x2T tail (nt=10)
        #pragma unroll
        for (int s = 0; s < 4; s++) {
            uint32_t a0[4], a1[4];
            LDSM_X4(a0, rowA0 + s*32);
            LDSM_X4(a1, rowA0 + 16*144 + s*32);
            uint32_t soff = (uint32_t)s*2816;   // s*16*176
            #pragma unroll
            for (int ntp = 0; ntp < 5; ntp++) {
                uint32_t bf[4];
                LDSM_X4T(bf, rowB4 + soff + ntp*32);
                mma16816(acc[0][2*ntp],     a0, bf);
                mma16816(acc[1][2*ntp],     a1, bf);
                mma16816(acc[0][2*ntp + 1], a0, bf + 2);
                mma16816(acc[1][2*ntp + 1], a1, bf + 2);
            }
            {
                uint32_t bf[2];
                LDSM_X2T(bf, rowB2 + soff + 160);
                mma16816(acc[0][10], a0, bf);
                mma16816(acc[1][10], a1, bf);
            }
        }
        CP_WAIT0();
        __syncthreads();
    }

    // fragments -> sD[oc][m] (m = orow*128 + px); aliases sx+B (dead now)
    float* sD = (float*)(smem);
    {
        int n0 = (lane & 3)*2;
        int m0 = orow*128 + pxq + (lane >> 2);
        #pragma unroll
        for (int a = 0; a < 2; a++) {
            int m = m0 + a*16;
            #pragma unroll
            for (int nt = 0; nt < 11; nt++) {
                int n = nt*8 + n0;
                sD[n*264 + m]           = acc[a][nt][0];
                sD[(n + 1)*264 + m]     = acc[a][nt][1];
                sD[n*264 + m + 8]       = acc[a][nt][2];
                sD[(n + 1)*264 + m + 8] = acc[a][nt][3];
            }
        }
    }
    __syncthreads();

    // epilogue: 164 tasks = 82 oc x 2 rows
    float pa = pa_[0];
    for (int idx = wid; idx < 164; idx += 8) {
        int oc = idx >> 1, row = idx & 1;
        int h = h0 + row;
        float v[4];
        #pragma unroll
        for (int j = 0; j < 4; j++) v[j] = sD[oc*264 + row*128 + lane + 32*j];
        if (oc < 64) {
            float m = fmaxf(fmaxf(v[0], v[1]), fmaxf(v[2], v[3]));
            #pragma unroll
            for (int s = 16; s > 0; s >>= 1)
                m = fmaxf(m, __shfl_xor_sync(0xffffffffu, m, s));
            float e[4]; float sum = 0.f;
            #pragma unroll
            for (int j = 0; j < 4; j++) { e[j] = __expf(v[j] - m); sum += e[j]; }
            #pragma unroll
            for (int s = 16; s > 0; s >>= 1)
                sum += __shfl_xor_sync(0xffffffffu, sum, s);
            float inv = 1.0f / sum;
            int base = ((b*CC + oc)*HH + h)*WW + lane;
            #pragma unroll
            for (int j = 0; j < 4; j++) g_atten[base + 32*j] = e[j]*inv;
        } else {
            int o2 = oc - 64;
            float bo = offb[o2];
            int base = ((b*KOFF + o2)*HH + h)*WW + lane;
            #pragma unroll
            for (int j = 0; j < 4; j++) {
                float u = v[j] + bo;
                g_offset[base + 32*j] = u >= 0.f ? u : pa*u;
            }
        }
    }
}

// ---------------------------------------------------------------------------
// H2: deformable grouped conv (R14 winner, unchanged).
// ---------------------------------------------------------------------------
#define SFS 36
#define SWR 147
__global__ __launch_bounds__(256, 3) void k_deformH2(
    const float* __restrict__ x, const float* __restrict__ dw,
    const float* __restrict__ db, float* __restrict__ out)
{
    extern __shared__ char smH[];
    uint32_t* sco = (uint32_t*)smH;
    u64* sw2      = (u64*)(smH + 9216);
    float* sfeat  = (float*)(smH + 9216 + 16*SWR*8);

    int t = threadIdx.x;
    int b  = blockIdx.x >> 9;
    int h  = (blockIdx.x >> 2) & 127;
    int q  = blockIdx.x & 3;
    int px0 = q*32;

    for (int i = t; i < 288; i += 256) {
        int tap = i >> 5, pl = i & 31;
        int ky = tap / 3, kx = tap - ky*3;
        int w = px0 + pl;
        float dy = g_offset[(b*KOFF + 2*tap)*HWSZ + h*WW + w];
        float dx = g_offset[(b*KOFF + 2*tap + 1)*HWSZ + h*WW + w];
        float ys = (float)(h - 1 + ky) + dy;
        float xs = (float)(w - 1 + kx) + dx;
        float yf = floorf(ys), xf = floorf(xs);
        float ay = ys - yf, ax = xs - xf;
        int iy0 = (int)yf, ix0 = (int)xf;
        float my0 = (iy0 >= 0  && iy0 < HH)     ? 1.f : 0.f;
        float my1 = (iy0 >= -1 && iy0 + 1 < HH) ? 1.f : 0.f;
        float mx0 = (ix0 >= 0  && ix0 < WW)     ? 1.f : 0.f;
        float mx1 = (ix0 >= -1 && ix0 + 1 < WW) ? 1.f : 0.f;
        int cy0 = min(max(iy0, 0), HH - 1), cy1 = min(max(iy0 + 1, 0), HH - 1);
        int cx0 = min(max(ix0, 0), WW - 1), cx1 = min(max(ix0 + 1, 0), WW - 1);
        uint4 I = make_uint4((uint32_t)((cy0*WW + cx0)*CC),
                             (uint32_t)((cy0*WW + cx1)*CC),
                             (uint32_t)((cy1*WW + cx0)*CC),
                             (uint32_t)((cy1*WW + cx1)*CC));
        uint4 Cq = make_uint4(__float_as_uint((1.f - ay)*(1.f - ax)*my0*mx0),
                              __float_as_uint((1.f - ay)*ax*my0*mx1),
                              __float_as_uint(ay*(1.f - ax)*my1*mx0),
                              __float_as_uint(ay*ax*my1*mx1));
        *(uint4*)(sco + i*8)     = I;
        *(uint4*)(sco + i*8 + 4) = Cq;
    }
    for (int i = t; i < 16*9*16; i += 256) {
        int gh = i / 144; int rem = i - gh*144;
        int tap = rem >> 4; int j = rem & 15;
        int ci = j >> 2, p = j & 3;
        int g = gh >> 1, half = gh & 1;
        int base = ((g*8 + 2*p)*8 + half*4 + ci)*9 + tap;
        sw2[gh*SWR + tap*16 + ci*4 + p] = pk2(dw[base], dw[base + 72]);
    }
    __syncthreads();

    int pl = t >> 4, gh = t & 15;
    int g = gh >> 1, half = gh & 1;

    u64 acc0[4], acc1[4];
    #pragma unroll
    for (int p = 0; p < 4; p++) {
        u64 bo = half ? 0ULL : pk2(db[g*8 + 2*p], db[g*8 + 2*p + 1]);
        acc0[p] = bo; acc1[p] = bo;
    }

    const __nv_bfloat16* xgb = g_xtb + (size_t)b*HWSZ*CC + g*8 + half*4;
    const u64* sw2g = sw2 + gh*SWR;

    #pragma unroll 1
    for (int k = 0; k < 9; k++) {
        u64 W2[16];
        {
            const u64* wt = sw2g + k*16;
            #pragma unroll
            for (int j = 0; j < 16; j++) W2[j] = wt[j];
        }
        #pragma unroll
        for (int p2 = 0; p2 < 2; p2++) {
            int plo = pl + p2*16;
            u64* ac = p2 ? acc1 : acc0;
            uint4 I  = *(const uint4*)(sco + (k*32 + plo)*8);
            uint4 Cq = *(const uint4*)(sco + (k*32 + plo)*8 + 4);
            float c00 = __uint_as_float(Cq.x), c01 = __uint_as_float(Cq.y);
            float c10 = __uint_as_float(Cq.z), c11 = __uint_as_float(Cq.w);
            uint2 A  = *(const uint2*)(xgb + I.x);
            uint2 Bv = *(const uint2*)(xgb + I.y);
            uint2 Cv = *(const uint2*)(xgb + I.z);
            uint2 D  = *(const uint2*)(xgb + I.w);
            float s0 = c00*bfLO(A.x) + c01*bfLO(Bv.x) + c10*bfLO(Cv.x) + c11*bfLO(D.x);
            float s1 = c00*bfHI(A.x) + c01*bfHI(Bv.x) + c10*bfHI(Cv.x) + c11*bfHI(D.x);
            float s2 = c00*bfLO(A.y) + c01*bfLO(Bv.y) + c10*bfLO(Cv.y) + c11*bfLO(D.y);
            float s3 = c00*bfHI(A.y) + c01*bfHI(Bv.y) + c10*bfHI(Cv.y) + c11*bfHI(D.y);
            u64 sp;
            sp = pk2(s0, s0);
            ac[0] = fma2(W2[0],  sp, ac[0]); ac[1] = fma2(W2[1],  sp, ac[1]);
            ac[2] = fma2(W2[2],  sp, ac[2]); ac[3] = fma2(W2[3],  sp, ac[3]);
            sp = pk2(s1, s1);
            ac[0] = fma2(W2[4],  sp, ac[0]); ac[1] = fma2(W2[5],  sp, ac[1]);
            ac[2] = fma2(W2[6],  sp, ac[2]); ac[3] = fma2(W2[7],  sp, ac[3]);
            sp = pk2(s2, s2);
            ac[0] = fma2(W2[8],  sp, ac[0]); ac[1] = fma2(W2[9],  sp, ac[1]);
            ac[2] = fma2(W2[10], sp, ac[2]); ac[3] = fma2(W2[11], sp, ac[3]);
            sp = pk2(s3, s3);
            ac[0] = fma2(W2[12], sp, ac[0]); ac[1] = fma2(W2[13], sp, ac[1]);
            ac[2] = fma2(W2[14], sp, ac[2]); ac[3] = fma2(W2[15], sp, ac[3]);
        }
    }

    #pragma unroll
    for (int p = 0; p < 4; p++) {
        float2 a0 = uf2(acc0[p]), a1 = uf2(acc1[p]);
        a0.x += __shfl_xor_sync(0xffffffffu, a0.x, 1);
        a0.y += __shfl_xor_sync(0xffffffffu, a0.y, 1);
        a1.x += __shfl_xor_sync(0xffffffffu, a1.x, 1);
        a1.y += __shfl_xor_sync(0xffffffffu, a1.y, 1);
        if (half == 0) {
            sfeat[(g*8 + 2*p)*SFS + pl]          = a0.x;
            sfeat[(g*8 + 2*p + 1)*SFS + pl]      = a0.y;
            sfeat[(g*8 + 2*p)*SFS + pl + 16]     = a1.x;
            sfeat[(g*8 + 2*p + 1)*SFS + pl + 16] = a1.y;
        }
    }
    __syncthreads();

    #pragma unroll
    for (int it = 0; it < 2; it++) {
        int idx = t + it*256;
        int oc = idx >> 3, p4 = idx & 7;
        float4 f = *(const float4*)(sfeat + oc*SFS + p4*4);
        int base = ((b*CC + oc)*HH + h)*WW + px0 + p4*4;
        float4 at = *(const float4*)(g_atten + base);
        float4 xv = *(const float4*)(x + base);
        float4 ov = make_float4(fmaf(at.x, f.x, xv.x), fmaf(at.y, f.y, xv.y),
                                fmaf(at.z, f.z, xv.z), fmaf(at.w, f.w, xv.w));
        *(float4*)(out + base) = ov;
    }
}

extern "C" void kernel_launch(void* const* d_in, const int* in_sizes, int n_in,
                              void* d_out, int out_size)
{
    const float* x    = (const float*)d_in[0];
    const float* offw = (const float*)d_in[1];
    const float* offb = (const float*)d_in[2];
    const float* pa   = (const float*)d_in[3];
    const float* dw   = (const float*)d_in[4];
    const float* db   = (const float*)d_in[5];
    const float* cw   = (const float*)d_in[6];
    float* out = (float*)d_out;

    const int smemH = 9216 + 16*SWR*8 + 64*SFS*4;   // 37248

    cudaFuncSetAttribute(k_convMMA7, cudaFuncAttributeMaxDynamicSharedMemorySize, SMEM7);
    cudaFuncSetAttribute(k_deformH2, cudaFuncAttributeMaxDynamicSharedMemorySize, smemH);

    k_prepB<<<198, 256>>>(cw, offw);
    k_transpose<<<2048, 256>>>(x);
    k_dummy<<<1, 32>>>();
    k_convMMA7<<<512, 256, SMEM7>>>(offb, pa);         // 4th launch -> ncu capture
    k_deformH2<<<4096, 256, smemH>>>(x, dw, db, out);
}